// round 10
// baseline (speedup 1.0000x reference)
#include <cuda_runtime.h>
#include <cstdint>

#define TT 65536
#define KK 512
#define NEGV (-10000.0f)
#define CSZ 16            // cluster CTAs
#define NPC 32            // next-rows per CTA
#define NTHR 256          // 8 warps
#define LBT 256
#define BBT (TT/LBT)
#define STEP_TX (KK*4)    // 2048 B arriving per CTA per step
#define GG 64             // bp-pass t-partitions (1024 CTAs)
#define SPAN (TT/GG)

// ---- static device scratch ----
__device__ float          g_fv[(size_t)TT * KK];   // fv history
__device__ unsigned short g_bp[(size_t)TT * KK];   // backpointers
__device__ unsigned short g_maps[BBT * KK];
__device__ int            g_endtag[BBT];
__device__ int            g_best;

__device__ __forceinline__ uint32_t smem_u32(const void* p) {
    return (uint32_t)__cvta_generic_to_shared(p);
}
__device__ __forceinline__ uint32_t mapa_u32(uint32_t laddr, int r) {
    uint32_t ra;
    asm("mapa.shared::cluster.u32 %0, %1, %2;" : "=r"(ra) : "r"(laddr), "r"(r));
    return ra;
}
__device__ __forceinline__ void st_async_b64(uint32_t raddr, unsigned long long v,
                                             uint32_t rmbar) {
    asm volatile(
        "st.async.weak.shared::cluster.mbarrier::complete_tx::bytes.b64 [%0], %1, [%2];"
        :: "r"(raddr), "l"(v), "r"(rmbar) : "memory");
}
__device__ __forceinline__ void mbar_init(uint32_t a, uint32_t cnt) {
    asm volatile("mbarrier.init.shared.b64 [%0], %1;" :: "r"(a), "r"(cnt) : "memory");
}
__device__ __forceinline__ void mbar_expect_tx(uint32_t a, uint32_t bytes) {
    asm volatile("mbarrier.arrive.expect_tx.shared.b64 _, [%0], %1;"
                 :: "r"(a), "r"(bytes) : "memory");
}
__device__ __forceinline__ void mbar_wait(uint32_t a, uint32_t parity) {
    uint32_t done;
    asm volatile(
        "{\n\t.reg .pred p;\n\t"
        "mbarrier.try_wait.parity.acquire.cta.shared::cta.b64 p, [%1], %2;\n\t"
        "selp.b32 %0, 1, 0, p;\n\t}"
        : "=r"(done) : "r"(a), "r"(parity) : "memory");
    if (!done) {
        asm volatile(
            "{\n\t.reg .pred P1;\n\t"
            "W_%=:\n\t"
            "mbarrier.try_wait.parity.acquire.cta.shared::cta.b64 P1, [%0], %1, 0x989680;\n\t"
            "@P1 bra.uni D_%=;\n\t"
            "bra.uni W_%=;\n\t"
            "D_%=:\n\t}"
            :: "r"(a), "r"(parity) : "memory");
    }
}
__device__ __forceinline__ void cluster_sync_() {
    asm volatile("barrier.cluster.arrive.aligned;" ::: "memory");
    asm volatile("barrier.cluster.wait.aligned;" ::: "memory");
}
__device__ __forceinline__ uint32_t ctarank() {
    uint32_t r; asm("mov.u32 %0, %%cluster_ctarank;" : "=r"(r)); return r;
}
// transposed slot: conflict-free for chunked float4 reads
__device__ __forceinline__ uint32_t slotbyte(int p) {
    return (uint32_t)(((p & 63) >> 2) * 128 + (p >> 6) * 16 + (p & 3) * 4);
}

// ---- kernel 1: per-warp autonomous value-only forward pass ----
__global__ void __launch_bounds__(NTHR, 1)
viterbi_fwd(const float* __restrict__ feats, const float* __restrict__ trans,
            float* __restrict__ dout, int idx0)
{
    __shared__ __align__(16) float fvt[2][KK];   // transposed; buf1 at +2048B
    __shared__ __align__(8)  unsigned long long mbar[2];
    __shared__ float tv[NTHR];
    __shared__ int   ti[NTHR];

    const int tid   = threadIdx.x;
    const int lane  = tid & 31;
    const int w     = tid >> 5;        // warp w: rows 4w..4w+3
    const int rl    = lane & 3;
    const int chunk = lane >> 2;       // prev chunk 0..7
    const uint32_t rank = ctarank();
    const int n = (int)rank * NPC + w * 4 + rl;

    // transitions slice trans[n, chunk*64 .. +64) -> registers
    float Tr[64];
    {
        const float4* tp = (const float4*)(trans + (size_t)n * KK + chunk * 64);
        #pragma unroll
        for (int q = 0; q < 16; q++) {
            float4 v = tp[q];
            Tr[4*q] = v.x; Tr[4*q+1] = v.y; Tr[4*q+2] = v.z; Tr[4*q+3] = v.w;
        }
    }

    // init: fv_{-1} in buf[1] (step t reads buf[(t+1)&1]) — transposed layout
    const uint32_t base = smem_u32(&fvt[0][0]);
    for (int p = tid; p < KK; p += NTHR) {
        *(float*)((char*)&fvt[0][0] + 2048u + slotbyte(p)) = (p == 0) ? 0.0f : NEGV;
    }
    if (tid == 0) { mbar_init(smem_u32(&mbar[0]), 1); mbar_init(smem_u32(&mbar[1]), 1); }
    __syncthreads();
    cluster_sync_();

    const uint32_t mb0 = smem_u32(&mbar[0]);
    const uint32_t mb1 = smem_u32(&mbar[1]);
    const uint32_t rbase = base + (uint32_t)chunk * 16u;   // + q*128 per load

    // push addresses: lanes rl even, chunk==0 push rows (n, n+1) to all CTAs
    uint32_t rdst[CSZ], rmbl[CSZ];
    {
        const uint32_t a0 = base + slotbyte(n);   // n: rl even => 8B aligned slot
        #pragma unroll
        for (int r = 0; r < CSZ; r++) { rdst[r] = mapa_u32(a0, r); rmbl[r] = mapa_u32(mb0, r); }
    }

    // feats prefetch (chunk==0 lanes use it; row = n)
    float ft0 = 0.0f, ft1 = 0.0f;
    if (chunk == 0) {
        ft0 = __ldg(feats + n);
        ft1 = __ldg(feats + KK + n);
    }

    #define STEP(T, PAR) do {                                                      \
        if (tid == 0) mbar_expect_tx((PAR) ? mb1 : mb0, STEP_TX);                  \
        float ftn = 0.0f;                                                          \
        if (chunk == 0) {                                                          \
            int tn = (T) + 2; if (tn > TT - 1) tn = TT - 1;                        \
            ftn = __ldg(feats + (size_t)tn * KK + n);                              \
        }                                                                          \
        const uint32_t rb = rbase + ((PAR) ^ 1) * 2048u;                           \
        float m0 = -INFINITY, m1 = -INFINITY, m2 = -INFINITY, m3 = -INFINITY;      \
        _Pragma("unroll")                                                          \
        for (int q = 0; q < 16; q++) {                                             \
            float4 f;                                                              \
            asm volatile("ld.shared.v4.f32 {%0,%1,%2,%3}, [%4];"                   \
                : "=f"(f.x), "=f"(f.y), "=f"(f.z), "=f"(f.w)                       \
                : "r"(rb + (uint32_t)q * 128u));                                   \
            m0 = fmaxf(m0, f.x + Tr[4*q]);                                         \
            m1 = fmaxf(m1, f.y + Tr[4*q+1]);                                       \
            m2 = fmaxf(m2, f.z + Tr[4*q+2]);                                       \
            m3 = fmaxf(m3, f.w + Tr[4*q+3]);                                       \
        }                                                                          \
        float v = fmaxf(fmaxf(m0, m1), fmaxf(m2, m3));                             \
        v = fmaxf(v, __shfl_xor_sync(0xffffffffu, v, 4));                          \
        v = fmaxf(v, __shfl_xor_sync(0xffffffffu, v, 8));                          \
        v = fmaxf(v, __shfl_xor_sync(0xffffffffu, v, 16));                         \
        if (chunk == 0) {                     /* lanes 0-3 own rows 4w..4w+3 */    \
            const float fvnew = v + ft0;      /* exact: max + emission */          \
            const float fhi = __shfl_down_sync(0x0000000fu, fvnew, 1);             \
            if ((rl & 1) == 0) {                                                   \
                *(float2*)&g_fv[(size_t)(T) * KK + n] = make_float2(fvnew, fhi);   \
                unsigned long long pk =                                            \
                    ((unsigned long long)__float_as_uint(fhi) << 32) |             \
                    (unsigned long long)__float_as_uint(fvnew);                    \
                _Pragma("unroll")                                                  \
                for (int r = 0; r < CSZ; r++)                                      \
                    st_async_b64(rdst[r] + (PAR)*2048u, pk, rmbl[r] + (PAR)*8u);   \
            }                                                                      \
            ft0 = ft1; ft1 = ftn;                                                  \
        }                                                                          \
        if (w == 0) mbar_wait((PAR) ? mb1 : mb0, ((T) >> 1) & 1);                  \
        __syncthreads();                                                           \
    } while (0)

    for (int t = 0; t < TT; t += 2) {
        STEP(t, 0);
        STEP(t + 1, 1);
    }
    #undef STEP

    // terminal = fv_{TT-1} + trans[1,:]; first-index argmax (rank 0)
    if (rank == 0) {
        float v = -INFINITY; int i = 0;
        #pragma unroll
        for (int k = 0; k < 2; k++) {
            const int p = 2 * tid + k;     // ascending p per tid, tid-major
            const float fvv = *(const float*)((const char*)&fvt[0][0] + 2048u + slotbyte(p));
            const float s = fvv + trans[KK + p];
            if (s > v) { v = s; i = p; }
        }
        tv[tid] = v; ti[tid] = i;
        __syncthreads();
        if (tid == 0) {
            float bv = tv[0]; int bi = ti[0];
            for (int k = 1; k < NTHR; k++)
                if (tv[k] > bv || (tv[k] == bv && ti[k] < bi)) { bv = tv[k]; bi = ti[k]; }
            if (idx0 > 0) dout[0] = bv;
            g_best = bi;
        }
    }
    cluster_sync_();   // keep cluster alive until all remote traffic done
}

// ---- kernel 2: parallel backpointer recompute (exact argmax) ----
__global__ void __launch_bounds__(NTHR, 1)
bp_pass(const float* __restrict__ trans)
{
    __shared__ __align__(16) float fvs[2][KK];   // transposed staging

    const int rblk = blockIdx.x & 15;
    const int g    = blockIdx.x >> 4;
    const int t0   = g * SPAN;
    const int t1   = t0 + SPAN;

    const int tid   = threadIdx.x;
    const int lane  = tid & 31;
    const int w     = tid >> 5;
    const int rl    = lane & 3;
    const int chunk = lane >> 2;
    const int n = rblk * NPC + w * 4 + rl;

    float Tr[64];
    {
        const float4* tp = (const float4*)(trans + (size_t)n * KK + chunk * 64);
        #pragma unroll
        for (int q = 0; q < 16; q++) {
            float4 v = tp[q];
            Tr[4*q] = v.x; Tr[4*q+1] = v.y; Tr[4*q+2] = v.z; Tr[4*q+3] = v.w;
        }
    }

    const int sp = 2 * tid;
    const uint32_t sbyte = (uint32_t)(((sp & 63) >> 2) * 128 + (sp >> 6) * 16 + (sp & 3) * 4);

    float2 pre;
    if (t0 == 0) {
        pre.x = (sp == 0) ? 0.0f : NEGV;
        pre.y = NEGV;
    } else {
        pre = *(const float2*)&g_fv[(size_t)(t0 - 1) * KK + sp];
    }

    int cur = 0;
    for (int t = t0; t < t1; ++t) {
        *(float2*)((char*)&fvs[cur][0] + sbyte) = pre;
        __syncthreads();
        if (t + 1 < t1) pre = *(const float2*)&g_fv[(size_t)t * KK + sp];

        const char* sm = (const char*)&fvs[cur][0] + chunk * 16;
        float bv0 = -INFINITY, bv1 = -INFINITY, bv2 = -INFINITY, bv3 = -INFINITY;
        int   bj0 = 0, bj1 = 0, bj2 = 0, bj3 = 0;
        #pragma unroll
        for (int q = 0; q < 16; q++) {
            float4 f = *(const float4*)(sm + q * 128);
            float s0 = f.x + Tr[4*q],   s1 = f.y + Tr[4*q+1];
            float s2 = f.z + Tr[4*q+2], s3 = f.w + Tr[4*q+3];
            bool g0 = s0 > bv0; bv0 = g0 ? s0 : bv0; bj0 = g0 ? 4*q : bj0;
            bool g1 = s1 > bv1; bv1 = g1 ? s1 : bv1; bj1 = g1 ? 4*q : bj1;
            bool g2 = s2 > bv2; bv2 = g2 ? s2 : bv2; bj2 = g2 ? 4*q : bj2;
            bool g3 = s3 > bv3; bv3 = g3 ? s3 : bv3; bj3 = g3 ? 4*q : bj3;
        }
        int i0 = chunk*64 + bj0, i1 = chunk*64 + bj1 + 1;
        int i2 = chunk*64 + bj2 + 2, i3 = chunk*64 + bj3 + 3;
        if (bv1 > bv0 || (bv1 == bv0 && i1 < i0)) { bv0 = bv1; i0 = i1; }
        if (bv3 > bv2 || (bv3 == bv2 && i3 < i2)) { bv2 = bv3; i2 = i3; }
        if (bv2 > bv0 || (bv2 == bv0 && i2 < i0)) { bv0 = bv2; i0 = i2; }

        float v = bv0; int i = i0;
        #pragma unroll
        for (int d = 4; d <= 16; d <<= 1) {
            float vo = __shfl_xor_sync(0xffffffffu, v, d);
            int   io = __shfl_xor_sync(0xffffffffu, i, d);
            if (vo > v || (vo == v && io < i)) { v = vo; i = io; }
        }
        if (chunk == 0)
            g_bp[(size_t)t * KK + n] = (unsigned short)i;
        cur ^= 1;
    }
}

// ---- kernel 3: per-block backtrack maps ----
__global__ void bt_maps()
{
    __shared__ unsigned short rbuf[KK];
    const int b = blockIdx.x, tid = threadIdx.x;
    int x = tid;
    for (int s = LBT - 1; s >= 0; --s) {
        const size_t t = (size_t)b * LBT + s;
        rbuf[tid] = g_bp[t * KK + tid];
        __syncthreads();
        x = rbuf[x];
        __syncthreads();
    }
    g_maps[b * KK + tid] = (unsigned short)x;
}

// ---- kernel 4: compose block maps ----
__global__ void bt_compose()
{
    int e = g_best;
    g_endtag[BBT - 1] = e;
    for (int b = BBT - 1; b >= 1; --b) {
        e = g_maps[b * KK + e];
        g_endtag[b - 1] = e;
    }
}

// ---- kernel 5: fill best_path ----
__global__ void bt_fill(float* __restrict__ dout, int idx0)
{
    const int b = blockIdx.x;
    int x = g_endtag[b];
    for (int s = LBT - 1; s >= 0; --s) {
        const size_t t = (size_t)b * LBT + s;
        dout[idx0 + t] = (float)x;
        x = g_bp[t * KK + x];
    }
}

extern "C" void kernel_launch(void* const* d_in, const int* in_sizes, int n_in,
                              void* d_out, int out_size)
{
    const float* feats = (const float*)d_in[0];
    const float* trans = (const float*)d_in[1];
    float* out = (float*)d_out;
    int idx0 = out_size - TT; if (idx0 < 0) idx0 = 0;

    cudaFuncSetAttribute(viterbi_fwd,
                         cudaFuncAttributeNonPortableClusterSizeAllowed, 1);
    cudaLaunchConfig_t cfg = {};
    cfg.gridDim  = dim3(CSZ, 1, 1);
    cfg.blockDim = dim3(NTHR, 1, 1);
    cfg.dynamicSmemBytes = 0;
    cfg.stream = 0;
    cudaLaunchAttribute at[1];
    at[0].id = cudaLaunchAttributeClusterDimension;
    at[0].val.clusterDim.x = CSZ;
    at[0].val.clusterDim.y = 1;
    at[0].val.clusterDim.z = 1;
    cfg.attrs = at; cfg.numAttrs = 1;
    cudaLaunchKernelEx(&cfg, viterbi_fwd, feats, trans, out, idx0);

    bp_pass<<<16 * GG, NTHR>>>(trans);
    bt_maps<<<BBT, KK>>>();
    bt_compose<<<1, 1>>>();
    bt_fill<<<BBT, 1>>>(out, idx0);
}

// round 11
// speedup vs baseline: 1.5753x; 1.5753x over previous
#include <cuda_runtime.h>
#include <cstdint>

#define TT 65536
#define KK 512
#define NEGV (-10000.0f)
#define CSZ 16            // cluster CTAs
#define NPC 32            // next-rows per CTA
#define NTHR 256          // 8 warps
#define LBT 256
#define BBT (TT/LBT)
#define STEP_TX (KK*4)    // 2048 B arriving per CTA per step
#define GG 64             // bp-pass t-partitions (1024 CTAs)
#define SPAN (TT/GG)

// ---- static device scratch ----
__device__ float          g_fv[(size_t)TT * KK];   // fv history
__device__ unsigned short g_bp[(size_t)TT * KK];   // backpointers
__device__ unsigned short g_maps[BBT * KK];
__device__ int            g_endtag[BBT];
__device__ int            g_best;

__device__ __forceinline__ uint32_t smem_u32(const void* p) {
    return (uint32_t)__cvta_generic_to_shared(p);
}
__device__ __forceinline__ uint32_t mapa_u32(uint32_t laddr, int r) {
    uint32_t ra;
    asm("mapa.shared::cluster.u32 %0, %1, %2;" : "=r"(ra) : "r"(laddr), "r"(r));
    return ra;
}
__device__ __forceinline__ void st_async_b64(uint32_t raddr, unsigned long long v,
                                             uint32_t rmbar) {
    asm volatile(
        "st.async.weak.shared::cluster.mbarrier::complete_tx::bytes.b64 [%0], %1, [%2];"
        :: "r"(raddr), "l"(v), "r"(rmbar) : "memory");
}
__device__ __forceinline__ void mbar_init(uint32_t a, uint32_t cnt) {
    asm volatile("mbarrier.init.shared.b64 [%0], %1;" :: "r"(a), "r"(cnt) : "memory");
}
__device__ __forceinline__ void mbar_expect_tx(uint32_t a, uint32_t bytes) {
    asm volatile("mbarrier.arrive.expect_tx.shared.b64 _, [%0], %1;"
                 :: "r"(a), "r"(bytes) : "memory");
}
__device__ __forceinline__ void mbar_wait(uint32_t a, uint32_t parity) {
    uint32_t done;
    asm volatile(
        "{\n\t.reg .pred p;\n\t"
        "mbarrier.try_wait.parity.acquire.cta.shared::cta.b64 p, [%1], %2;\n\t"
        "selp.b32 %0, 1, 0, p;\n\t}"
        : "=r"(done) : "r"(a), "r"(parity) : "memory");
    if (!done) {
        asm volatile(
            "{\n\t.reg .pred P1;\n\t"
            "W_%=:\n\t"
            "mbarrier.try_wait.parity.acquire.cta.shared::cta.b64 P1, [%0], %1, 0x989680;\n\t"
            "@P1 bra.uni D_%=;\n\t"
            "bra.uni W_%=;\n\t"
            "D_%=:\n\t}"
            :: "r"(a), "r"(parity) : "memory");
    }
}
__device__ __forceinline__ void cluster_sync_() {
    asm volatile("barrier.cluster.arrive.aligned;" ::: "memory");
    asm volatile("barrier.cluster.wait.aligned;" ::: "memory");
}
__device__ __forceinline__ uint32_t ctarank() {
    uint32_t r; asm("mov.u32 %0, %%cluster_ctarank;" : "=r"(r)); return r;
}

// ---- kernel 1: value-only forward; broadcast reads; distributed reduce+push ----
__global__ void __launch_bounds__(NTHR, 1)
viterbi_fwd(const float* __restrict__ feats, const float* __restrict__ trans,
            float* __restrict__ dout, int idx0)
{
    __shared__ __align__(16) float fvbuf[2][KK];   // plain layout; buf1 at +2048B
    __shared__ float pval[8][NPC];                 // per-chunk partial maxes
    __shared__ __align__(8) unsigned long long mbar[2];
    __shared__ float tv[NTHR];
    __shared__ int   ti[NTHR];

    const int tid  = threadIdx.x;
    const int lane = tid & 31;      // next-row within CTA
    const int w    = tid >> 5;      // warp w == prev chunk w
    const uint32_t rank = ctarank();
    const int n = (int)rank * NPC + lane;

    // transitions slice trans[n, w*64 .. +64) -> registers (broadcast-read layout)
    float Tr[64];
    {
        const float4* tp = (const float4*)(trans + (size_t)n * KK + w * 64);
        #pragma unroll
        for (int q = 0; q < 16; q++) {
            float4 v = tp[q];
            Tr[4*q] = v.x; Tr[4*q+1] = v.y; Tr[4*q+2] = v.z; Tr[4*q+3] = v.w;
        }
    }

    // init: fv_{-1} in buf[1] (step t reads buf[(t+1)&1])
    for (int p = tid; p < KK; p += NTHR) fvbuf[1][p] = (p == 0) ? 0.0f : NEGV;
    if (tid == 0) { mbar_init(smem_u32(&mbar[0]), 1); mbar_init(smem_u32(&mbar[1]), 1); }
    __syncthreads();
    cluster_sync_();

    const uint32_t mb0 = smem_u32(&mbar[0]);
    const uint32_t mb1 = smem_u32(&mbar[1]);

    // distributed push: warp w targets CTAs 2w and 2w+1; even lanes carry rows (n, n+1)
    uint32_t rd0, rd1, rm0, rm1;
    {
        const uint32_t a0 = smem_u32(&fvbuf[0][n]);   // n even for pushing lanes
        rd0 = mapa_u32(a0, 2 * w);
        rd1 = mapa_u32(a0, 2 * w + 1);
        rm0 = mapa_u32(mb0, 2 * w);
        rm1 = mapa_u32(mb0, 2 * w + 1);
    }

    // feats prefetch (all warps; row = n, redundant across warps -> L1 broadcast)
    float ft0 = __ldg(feats + n);
    float ft1 = __ldg(feats + KK + n);

    #define STEP(T, PAR) do {                                                      \
        if (tid == 0) mbar_expect_tx((PAR) ? mb1 : mb0, STEP_TX);                  \
        float ftn;                                                                 \
        {                                                                          \
            int tn = (T) + 2; if (tn > TT - 1) tn = TT - 1;                        \
            ftn = __ldg(feats + (size_t)tn * KK + n);                              \
        }                                                                          \
        const float4* fvp = (const float4*)&fvbuf[(PAR) ^ 1][w * 64];              \
        float m0 = -INFINITY, m1 = -INFINITY, m2 = -INFINITY, m3 = -INFINITY;      \
        _Pragma("unroll")                                                          \
        for (int q = 0; q < 16; q++) {                                             \
            float4 f = fvp[q];            /* 32-lane broadcast, conflict-free */   \
            m0 = fmaxf(m0, f.x + Tr[4*q]);                                         \
            m1 = fmaxf(m1, f.y + Tr[4*q+1]);                                       \
            m2 = fmaxf(m2, f.z + Tr[4*q+2]);                                       \
            m3 = fmaxf(m3, f.w + Tr[4*q+3]);                                       \
        }                                                                          \
        pval[w][lane] = fmaxf(fmaxf(m0, m1), fmaxf(m2, m3));                       \
        __syncthreads();                                                           \
        {                                                                          \
            float v = pval[0][lane];        /* all warps: identical reduce */      \
            _Pragma("unroll")                                                      \
            for (int c = 1; c < 8; c++) v = fmaxf(v, pval[c][lane]);               \
            const float fvnew = v + ft0;          /* exact: max + emission */      \
            const float fhi = __shfl_down_sync(0xffffffffu, fvnew, 1);             \
            if ((lane & 1) == 0) {                                                 \
                if (w == 0)                                                        \
                    *(float2*)&g_fv[(size_t)(T) * KK + n] = make_float2(fvnew, fhi);\
                unsigned long long pk =                                            \
                    ((unsigned long long)__float_as_uint(fhi) << 32) |             \
                    (unsigned long long)__float_as_uint(fvnew);                    \
                st_async_b64(rd0 + (PAR)*2048u, pk, rm0 + (PAR)*8u);               \
                st_async_b64(rd1 + (PAR)*2048u, pk, rm1 + (PAR)*8u);               \
            }                                                                      \
        }                                                                          \
        ft0 = ft1; ft1 = ftn;                                                      \
        if (w == 0) mbar_wait((PAR) ? mb1 : mb0, ((T) >> 1) & 1);                  \
        __syncthreads();                                                           \
    } while (0)

    for (int t = 0; t < TT; t += 2) {
        STEP(t, 0);
        STEP(t + 1, 1);
    }
    #undef STEP

    // terminal = fv_{TT-1} + trans[1,:]; first-index argmax (rank 0)
    if (rank == 0) {
        float v = -INFINITY; int i = 0;
        #pragma unroll
        for (int k = 0; k < KK / NTHR; k++) {
            const int p = tid * (KK / NTHR) + k;
            const float s = fvbuf[1][p] + trans[KK + p];
            if (s > v) { v = s; i = p; }
        }
        tv[tid] = v; ti[tid] = i;
        __syncthreads();
        if (tid == 0) {
            float bv = tv[0]; int bi = ti[0];
            for (int k = 1; k < NTHR; k++)
                if (tv[k] > bv || (tv[k] == bv && ti[k] < bi)) { bv = tv[k]; bi = ti[k]; }
            if (idx0 > 0) dout[0] = bv;
            g_best = bi;
        }
    }
    cluster_sync_();   // keep cluster alive until all remote traffic done
}

// ---- kernel 2: parallel backpointer recompute (exact argmax) ----
__global__ void __launch_bounds__(NTHR, 1)
bp_pass(const float* __restrict__ trans)
{
    // transposed conflict-free staging: float at ((p&63)>>2)*128 + (p>>6)*16 + (p&3)*4
    __shared__ __align__(16) float fvs[2][KK];

    const int rblk = blockIdx.x & 15;
    const int g    = blockIdx.x >> 4;
    const int t0   = g * SPAN;
    const int t1   = t0 + SPAN;

    const int tid   = threadIdx.x;
    const int lane  = tid & 31;
    const int w     = tid >> 5;
    const int rl    = lane & 3;
    const int chunk = lane >> 2;
    const int n = rblk * NPC + w * 4 + rl;

    float Tr[64];
    {
        const float4* tp = (const float4*)(trans + (size_t)n * KK + chunk * 64);
        #pragma unroll
        for (int q = 0; q < 16; q++) {
            float4 v = tp[q];
            Tr[4*q] = v.x; Tr[4*q+1] = v.y; Tr[4*q+2] = v.z; Tr[4*q+3] = v.w;
        }
    }

    const int sp = 2 * tid;
    const uint32_t sbyte = (uint32_t)(((sp & 63) >> 2) * 128 + (sp >> 6) * 16 + (sp & 3) * 4);

    float2 pre;
    if (t0 == 0) {
        pre.x = (sp == 0) ? 0.0f : NEGV;
        pre.y = NEGV;
    } else {
        pre = *(const float2*)&g_fv[(size_t)(t0 - 1) * KK + sp];
    }

    int cur = 0;
    for (int t = t0; t < t1; ++t) {
        *(float2*)((char*)&fvs[cur][0] + sbyte) = pre;
        __syncthreads();
        if (t + 1 < t1) pre = *(const float2*)&g_fv[(size_t)t * KK + sp];

        const char* sm = (const char*)&fvs[cur][0] + chunk * 16;
        float bv0 = -INFINITY, bv1 = -INFINITY, bv2 = -INFINITY, bv3 = -INFINITY;
        int   bj0 = 0, bj1 = 0, bj2 = 0, bj3 = 0;
        #pragma unroll
        for (int q = 0; q < 16; q++) {
            float4 f = *(const float4*)(sm + q * 128);
            float s0 = f.x + Tr[4*q],   s1 = f.y + Tr[4*q+1];
            float s2 = f.z + Tr[4*q+2], s3 = f.w + Tr[4*q+3];
            bool g0 = s0 > bv0; bv0 = g0 ? s0 : bv0; bj0 = g0 ? 4*q : bj0;
            bool g1 = s1 > bv1; bv1 = g1 ? s1 : bv1; bj1 = g1 ? 4*q : bj1;
            bool g2 = s2 > bv2; bv2 = g2 ? s2 : bv2; bj2 = g2 ? 4*q : bj2;
            bool g3 = s3 > bv3; bv3 = g3 ? s3 : bv3; bj3 = g3 ? 4*q : bj3;
        }
        int i0 = chunk*64 + bj0, i1 = chunk*64 + bj1 + 1;
        int i2 = chunk*64 + bj2 + 2, i3 = chunk*64 + bj3 + 3;
        if (bv1 > bv0 || (bv1 == bv0 && i1 < i0)) { bv0 = bv1; i0 = i1; }
        if (bv3 > bv2 || (bv3 == bv2 && i3 < i2)) { bv2 = bv3; i2 = i3; }
        if (bv2 > bv0 || (bv2 == bv0 && i2 < i0)) { bv0 = bv2; i0 = i2; }

        float v = bv0; int i = i0;
        #pragma unroll
        for (int d = 4; d <= 16; d <<= 1) {
            float vo = __shfl_xor_sync(0xffffffffu, v, d);
            int   io = __shfl_xor_sync(0xffffffffu, i, d);
            if (vo > v || (vo == v && io < i)) { v = vo; i = io; }
        }
        if (chunk == 0)
            g_bp[(size_t)t * KK + n] = (unsigned short)i;
        cur ^= 1;
    }
}

// ---- kernel 3: per-block backtrack maps ----
__global__ void bt_maps()
{
    __shared__ unsigned short rbuf[KK];
    const int b = blockIdx.x, tid = threadIdx.x;
    int x = tid;
    for (int s = LBT - 1; s >= 0; --s) {
        const size_t t = (size_t)b * LBT + s;
        rbuf[tid] = g_bp[t * KK + tid];
        __syncthreads();
        x = rbuf[x];
        __syncthreads();
    }
    g_maps[b * KK + tid] = (unsigned short)x;
}

// ---- kernel 4: compose block maps ----
__global__ void bt_compose()
{
    int e = g_best;
    g_endtag[BBT - 1] = e;
    for (int b = BBT - 1; b >= 1; --b) {
        e = g_maps[b * KK + e];
        g_endtag[b - 1] = e;
    }
}

// ---- kernel 5: fill best_path ----
__global__ void bt_fill(float* __restrict__ dout, int idx0)
{
    const int b = blockIdx.x;
    int x = g_endtag[b];
    for (int s = LBT - 1; s >= 0; --s) {
        const size_t t = (size_t)b * LBT + s;
        dout[idx0 + t] = (float)x;
        x = g_bp[t * KK + x];
    }
}

extern "C" void kernel_launch(void* const* d_in, const int* in_sizes, int n_in,
                              void* d_out, int out_size)
{
    const float* feats = (const float*)d_in[0];
    const float* trans = (const float*)d_in[1];
    float* out = (float*)d_out;
    int idx0 = out_size - TT; if (idx0 < 0) idx0 = 0;

    cudaFuncSetAttribute(viterbi_fwd,
                         cudaFuncAttributeNonPortableClusterSizeAllowed, 1);
    cudaLaunchConfig_t cfg = {};
    cfg.gridDim  = dim3(CSZ, 1, 1);
    cfg.blockDim = dim3(NTHR, 1, 1);
    cfg.dynamicSmemBytes = 0;
    cfg.stream = 0;
    cudaLaunchAttribute at[1];
    at[0].id = cudaLaunchAttributeClusterDimension;
    at[0].val.clusterDim.x = CSZ;
    at[0].val.clusterDim.y = 1;
    at[0].val.clusterDim.z = 1;
    cfg.attrs = at; cfg.numAttrs = 1;
    cudaLaunchKernelEx(&cfg, viterbi_fwd, feats, trans, out, idx0);

    bp_pass<<<16 * GG, NTHR>>>(trans);
    bt_maps<<<BBT, KK>>>();
    bt_compose<<<1, 1>>>();
    bt_fill<<<BBT, 1>>>(out, idx0);
}

// round 12
// speedup vs baseline: 1.7719x; 1.1248x over previous
#include <cuda_runtime.h>
#include <cstdint>

#define TT 65536
#define KK 512
#define NEGV (-10000.0f)
#define CSZ 16            // cluster CTAs
#define NPC 32            // next-rows per CTA
#define NTHR 256          // 8 warps
#define LBT 256
#define BBT (TT/LBT)
#define CH_TX 256u        // 32 msgs x 8B per chunk barrier per step
#define GG 64             // bp-pass t-partitions (1024 CTAs)
#define SPAN (TT/GG)

// ---- static device scratch ----
__device__ float          g_fv[(size_t)TT * KK];   // fv history
__device__ unsigned short g_bp[(size_t)TT * KK];   // backpointers
__device__ unsigned short g_maps[BBT * KK];
__device__ int            g_endtag[BBT];
__device__ int            g_best;

__device__ __forceinline__ uint32_t smem_u32(const void* p) {
    return (uint32_t)__cvta_generic_to_shared(p);
}
__device__ __forceinline__ uint32_t mapa_u32(uint32_t laddr, int r) {
    uint32_t ra;
    asm("mapa.shared::cluster.u32 %0, %1, %2;" : "=r"(ra) : "r"(laddr), "r"(r));
    return ra;
}
__device__ __forceinline__ void st_async_b64(uint32_t raddr, unsigned long long v,
                                             uint32_t rmbar) {
    asm volatile(
        "st.async.weak.shared::cluster.mbarrier::complete_tx::bytes.b64 [%0], %1, [%2];"
        :: "r"(raddr), "l"(v), "r"(rmbar) : "memory");
}
__device__ __forceinline__ void mbar_init(uint32_t a, uint32_t cnt) {
    asm volatile("mbarrier.init.shared.b64 [%0], %1;" :: "r"(a), "r"(cnt) : "memory");
}
__device__ __forceinline__ void mbar_expect_tx(uint32_t a, uint32_t bytes) {
    asm volatile("mbarrier.arrive.expect_tx.shared.b64 _, [%0], %1;"
                 :: "r"(a), "r"(bytes) : "memory");
}
__device__ __forceinline__ void mbar_complete_tx(uint32_t a, uint32_t bytes) {
    asm volatile("mbarrier.complete_tx.shared.b64 [%0], %1;"
                 :: "r"(a), "r"(bytes) : "memory");
}
__device__ __forceinline__ void mbar_wait(uint32_t a, uint32_t parity) {
    uint32_t done;
    asm volatile(
        "{\n\t.reg .pred p;\n\t"
        "mbarrier.try_wait.parity.acquire.cta.shared::cta.b64 p, [%1], %2;\n\t"
        "selp.b32 %0, 1, 0, p;\n\t}"
        : "=r"(done) : "r"(a), "r"(parity) : "memory");
    if (!done) {
        asm volatile(
            "{\n\t.reg .pred P1;\n\t"
            "W_%=:\n\t"
            "mbarrier.try_wait.parity.acquire.cta.shared::cta.b64 P1, [%0], %1, 0x989680;\n\t"
            "@P1 bra.uni D_%=;\n\t"
            "bra.uni W_%=;\n\t"
            "D_%=:\n\t}"
            :: "r"(a), "r"(parity) : "memory");
    }
}
__device__ __forceinline__ void cluster_sync_() {
    asm volatile("barrier.cluster.arrive.aligned;" ::: "memory");
    asm volatile("barrier.cluster.wait.aligned;" ::: "memory");
}
__device__ __forceinline__ uint32_t ctarank() {
    uint32_t r; asm("mov.u32 %0, %%cluster_ctarank;" : "=r"(r)); return r;
}

// ---- kernel 1: per-chunk-barrier dataflow forward pass (1 sync/step) ----
__global__ void __launch_bounds__(NTHR, 1)
viterbi_fwd(const float* __restrict__ feats, const float* __restrict__ trans,
            float* __restrict__ dout, int idx0)
{
    __shared__ __align__(16) float fvbuf[2][KK];        // buf1 at +2048B
    __shared__ float pval[2][8][NPC];                   // parity-double-buffered
    __shared__ __align__(8) unsigned long long cmbar[2][8];  // [parity][chunk]
    __shared__ float tv[NTHR];
    __shared__ int   ti[NTHR];

    const int tid  = threadIdx.x;
    const int lane = tid & 31;      // next-row within CTA
    const int w    = tid >> 5;      // warp w == prev chunk w
    const uint32_t rank = ctarank();
    const int n = (int)rank * NPC + lane;

    // transitions slice trans[n, w*64 .. +64) -> registers (broadcast-read layout)
    float Tr[64];
    {
        const float4* tp = (const float4*)(trans + (size_t)n * KK + w * 64);
        #pragma unroll
        for (int q = 0; q < 16; q++) {
            float4 v = tp[q];
            Tr[4*q] = v.x; Tr[4*q+1] = v.y; Tr[4*q+2] = v.z; Tr[4*q+3] = v.w;
        }
    }

    const uint32_t mbb = smem_u32(&cmbar[0][0]);   // [par][c] at mbb + par*64 + c*8

    // init fv_{-1} in buf[1]; init barriers; pre-complete [1][c] phase 0
    for (int p = tid; p < KK; p += NTHR) fvbuf[1][p] = (p == 0) ? 0.0f : NEGV;
    if (tid < 8) {
        mbar_init(mbb + (uint32_t)tid * 8u, 1);          // [0][tid]
        mbar_init(mbb + 64u + (uint32_t)tid * 8u, 1);    // [1][tid]
        mbar_expect_tx(mbb + 64u + (uint32_t)tid * 8u, CH_TX);
        mbar_complete_tx(mbb + 64u + (uint32_t)tid * 8u, CH_TX);
    }
    __syncthreads();
    cluster_sync_();

    // push: warp w -> dest CTAs 2w, 2w+1; even lanes carry rows (n, n+1);
    // dest chunk barrier index = rank>>1
    uint32_t rd0, rd1, rm0, rm1;
    {
        const uint32_t a0 = smem_u32(&fvbuf[0][n]);       // n even for pushing lanes
        const uint32_t mB = mbb + (rank >> 1) * 8u;       // [0][rank>>1]
        rd0 = mapa_u32(a0, 2 * w);
        rd1 = mapa_u32(a0, 2 * w + 1);
        rm0 = mapa_u32(mB, 2 * w);
        rm1 = mapa_u32(mB, 2 * w + 1);
    }
    const uint32_t myb = mbb + (uint32_t)w * 8u;          // my chunk barriers

    float ft0 = __ldg(feats + n);
    float ft1 = __ldg(feats + KK + n);

    #define STEP(T, PAR) do {                                                      \
        if (lane == 0) mbar_expect_tx(myb + (PAR)*64u, CH_TX);                     \
        float ftn;                                                                 \
        {                                                                          \
            int tn = (T) + 2; if (tn > TT - 1) tn = TT - 1;                        \
            ftn = __ldg(feats + (size_t)tn * KK + n);                              \
        }                                                                          \
        mbar_wait(myb + ((PAR)^1)*64u, ((T) >> 1) & 1);   /* my chunk ready */     \
        const float4* fvp = (const float4*)&fvbuf[(PAR) ^ 1][w * 64];              \
        float m0 = -INFINITY, m1 = -INFINITY, m2 = -INFINITY, m3 = -INFINITY;      \
        _Pragma("unroll")                                                          \
        for (int q = 0; q < 16; q++) {                                             \
            float4 f = fvp[q];            /* 32-lane broadcast, conflict-free */   \
            m0 = fmaxf(m0, f.x + Tr[4*q]);                                         \
            m1 = fmaxf(m1, f.y + Tr[4*q+1]);                                       \
            m2 = fmaxf(m2, f.z + Tr[4*q+2]);                                       \
            m3 = fmaxf(m3, f.w + Tr[4*q+3]);                                       \
        }                                                                          \
        pval[PAR][w][lane] = fmaxf(fmaxf(m0, m1), fmaxf(m2, m3));                  \
        __syncthreads();                                /* single sync per step */ \
        {                                                                          \
            float v = pval[PAR][0][lane];   /* all warps: identical reduce */      \
            _Pragma("unroll")                                                      \
            for (int c = 1; c < 8; c++) v = fmaxf(v, pval[PAR][c][lane]);          \
            const float fvnew = v + ft0;          /* exact: max + emission */      \
            const float fhi = __shfl_down_sync(0xffffffffu, fvnew, 1);             \
            if ((lane & 1) == 0) {                                                 \
                if (w == 0)                                                        \
                    *(float2*)&g_fv[(size_t)(T) * KK + n] = make_float2(fvnew, fhi);\
                unsigned long long pk =                                            \
                    ((unsigned long long)__float_as_uint(fhi) << 32) |             \
                    (unsigned long long)__float_as_uint(fvnew);                    \
                st_async_b64(rd0 + (PAR)*2048u, pk, rm0 + (PAR)*64u);              \
                st_async_b64(rd1 + (PAR)*2048u, pk, rm1 + (PAR)*64u);              \
            }                                                                      \
        }                                                                          \
        ft0 = ft1; ft1 = ftn;                                                      \
    } while (0)

    for (int t = 0; t < TT; t += 2) {
        STEP(t, 0);
        STEP(t + 1, 1);
    }
    #undef STEP

    // drain final-step messages (buf[1], barrier [1][w], phase TT/2 -> parity 0)
    mbar_wait(myb + 64u, (TT >> 1) & 1);
    __syncthreads();

    // terminal = fv_{TT-1} + trans[1,:]; first-index argmax (rank 0)
    if (rank == 0) {
        float v = -INFINITY; int i = 0;
        #pragma unroll
        for (int k = 0; k < KK / NTHR; k++) {
            const int p = tid * (KK / NTHR) + k;
            const float s = fvbuf[1][p] + trans[KK + p];
            if (s > v) { v = s; i = p; }
        }
        tv[tid] = v; ti[tid] = i;
        __syncthreads();
        if (tid == 0) {
            float bv = tv[0]; int bi = ti[0];
            for (int k = 1; k < NTHR; k++)
                if (tv[k] > bv || (tv[k] == bv && ti[k] < bi)) { bv = tv[k]; bi = ti[k]; }
            if (idx0 > 0) dout[0] = bv;
            g_best = bi;
        }
    }
    cluster_sync_();   // keep cluster alive until all remote traffic done
}

// ---- kernel 2: parallel backpointer recompute (exact argmax) ----
__global__ void __launch_bounds__(NTHR, 1)
bp_pass(const float* __restrict__ trans)
{
    __shared__ __align__(16) float fvs[2][KK];   // transposed staging

    const int rblk = blockIdx.x & 15;
    const int g    = blockIdx.x >> 4;
    const int t0   = g * SPAN;
    const int t1   = t0 + SPAN;

    const int tid   = threadIdx.x;
    const int lane  = tid & 31;
    const int w     = tid >> 5;
    const int rl    = lane & 3;
    const int chunk = lane >> 2;
    const int n = rblk * NPC + w * 4 + rl;

    float Tr[64];
    {
        const float4* tp = (const float4*)(trans + (size_t)n * KK + chunk * 64);
        #pragma unroll
        for (int q = 0; q < 16; q++) {
            float4 v = tp[q];
            Tr[4*q] = v.x; Tr[4*q+1] = v.y; Tr[4*q+2] = v.z; Tr[4*q+3] = v.w;
        }
    }

    const int sp = 2 * tid;
    const uint32_t sbyte = (uint32_t)(((sp & 63) >> 2) * 128 + (sp >> 6) * 16 + (sp & 3) * 4);

    float2 pre;
    if (t0 == 0) {
        pre.x = (sp == 0) ? 0.0f : NEGV;
        pre.y = NEGV;
    } else {
        pre = *(const float2*)&g_fv[(size_t)(t0 - 1) * KK + sp];
    }

    int cur = 0;
    for (int t = t0; t < t1; ++t) {
        *(float2*)((char*)&fvs[cur][0] + sbyte) = pre;
        __syncthreads();
        if (t + 1 < t1) pre = *(const float2*)&g_fv[(size_t)t * KK + sp];

        const char* sm = (const char*)&fvs[cur][0] + chunk * 16;
        float bv0 = -INFINITY, bv1 = -INFINITY, bv2 = -INFINITY, bv3 = -INFINITY;
        int   bj0 = 0, bj1 = 0, bj2 = 0, bj3 = 0;
        #pragma unroll
        for (int q = 0; q < 16; q++) {
            float4 f = *(const float4*)(sm + q * 128);
            float s0 = f.x + Tr[4*q],   s1 = f.y + Tr[4*q+1];
            float s2 = f.z + Tr[4*q+2], s3 = f.w + Tr[4*q+3];
            bool g0 = s0 > bv0; bv0 = g0 ? s0 : bv0; bj0 = g0 ? 4*q : bj0;
            bool g1 = s1 > bv1; bv1 = g1 ? s1 : bv1; bj1 = g1 ? 4*q : bj1;
            bool g2 = s2 > bv2; bv2 = g2 ? s2 : bv2; bj2 = g2 ? 4*q : bj2;
            bool g3 = s3 > bv3; bv3 = g3 ? s3 : bv3; bj3 = g3 ? 4*q : bj3;
        }
        int i0 = chunk*64 + bj0, i1 = chunk*64 + bj1 + 1;
        int i2 = chunk*64 + bj2 + 2, i3 = chunk*64 + bj3 + 3;
        if (bv1 > bv0 || (bv1 == bv0 && i1 < i0)) { bv0 = bv1; i0 = i1; }
        if (bv3 > bv2 || (bv3 == bv2 && i3 < i2)) { bv2 = bv3; i2 = i3; }
        if (bv2 > bv0 || (bv2 == bv0 && i2 < i0)) { bv0 = bv2; i0 = i2; }

        float v = bv0; int i = i0;
        #pragma unroll
        for (int d = 4; d <= 16; d <<= 1) {
            float vo = __shfl_xor_sync(0xffffffffu, v, d);
            int   io = __shfl_xor_sync(0xffffffffu, i, d);
            if (vo > v || (vo == v && io < i)) { v = vo; i = io; }
        }
        if (chunk == 0)
            g_bp[(size_t)t * KK + n] = (unsigned short)i;
        cur ^= 1;
    }
}

// ---- kernel 3: per-block backtrack maps ----
__global__ void bt_maps()
{
    __shared__ unsigned short rbuf[KK];
    const int b = blockIdx.x, tid = threadIdx.x;
    int x = tid;
    for (int s = LBT - 1; s >= 0; --s) {
        const size_t t = (size_t)b * LBT + s;
        rbuf[tid] = g_bp[t * KK + tid];
        __syncthreads();
        x = rbuf[x];
        __syncthreads();
    }
    g_maps[b * KK + tid] = (unsigned short)x;
}

// ---- kernel 4: compose block maps ----
__global__ void bt_compose()
{
    int e = g_best;
    g_endtag[BBT - 1] = e;
    for (int b = BBT - 1; b >= 1; --b) {
        e = g_maps[b * KK + e];
        g_endtag[b - 1] = e;
    }
}

// ---- kernel 5: fill best_path ----
__global__ void bt_fill(float* __restrict__ dout, int idx0)
{
    const int b = blockIdx.x;
    int x = g_endtag[b];
    for (int s = LBT - 1; s >= 0; --s) {
        const size_t t = (size_t)b * LBT + s;
        dout[idx0 + t] = (float)x;
        x = g_bp[t * KK + x];
    }
}

extern "C" void kernel_launch(void* const* d_in, const int* in_sizes, int n_in,
                              void* d_out, int out_size)
{
    const float* feats = (const float*)d_in[0];
    const float* trans = (const float*)d_in[1];
    float* out = (float*)d_out;
    int idx0 = out_size - TT; if (idx0 < 0) idx0 = 0;

    cudaFuncSetAttribute(viterbi_fwd,
                         cudaFuncAttributeNonPortableClusterSizeAllowed, 1);
    cudaLaunchConfig_t cfg = {};
    cfg.gridDim  = dim3(CSZ, 1, 1);
    cfg.blockDim = dim3(NTHR, 1, 1);
    cfg.dynamicSmemBytes = 0;
    cfg.stream = 0;
    cudaLaunchAttribute at[1];
    at[0].id = cudaLaunchAttributeClusterDimension;
    at[0].val.clusterDim.x = CSZ;
    at[0].val.clusterDim.y = 1;
    at[0].val.clusterDim.z = 1;
    cfg.attrs = at; cfg.numAttrs = 1;
    cudaLaunchKernelEx(&cfg, viterbi_fwd, feats, trans, out, idx0);

    bp_pass<<<16 * GG, NTHR>>>(trans);
    bt_maps<<<BBT, KK>>>();
    bt_compose<<<1, 1>>>();
    bt_fill<<<BBT, 1>>>(out, idx0);
}